// round 12
// baseline (speedup 1.0000x reference)
#include <cuda_runtime.h>
#include <cuda_fp16.h>
#include <cstdint>

// ============================================================================
// CLinear: out[M,N] = x[M,K] @ dequant(W)[N,K]^T + bias
// M=8192, N=4096, K=4096. Base-compute_103-safe: mma.sync fp16 + cp.async.
// R12: R11 (best: 591.6us) with the per-kt cp.async prefetch split into two
//      4-op halves issued after ks0 and after ks1 respectively, spreading LSU
//      issue across two MMA bursts.
// ============================================================================

#define K_DIM 4096
#define N_DIM 4096
#define NUM_GROUPS 64
#define M_MAX 8192

#define BM 128
#define BN 128
#define BK 64
#define KT_COUNT (K_DIM / BK)      // 64
#define STAGES 3
#define A_BYTES (BM * BK * 2)      // 16384
#define B_BYTES (BN * BK * 2)      // 16384
#define STAGE_BYTES (A_BYTES + B_BYTES)          // 32768
#define SMEM_TOTAL (STAGES * STAGE_BYTES)        // 98304 -> 2 CTAs/SM
#define NT 256

// fp16 scratch (device globals: the only legal scratch)
__device__ __half g_xh[(size_t)M_MAX * K_DIM];   // 64 MB
__device__ __half g_wh[(size_t)N_DIM * K_DIM];   // 32 MB

// ---------------------------------------------------------------------------
__device__ __forceinline__ uint32_t smem_u32(const void* p) {
    uint32_t a;
    asm("{ .reg .u64 t; cvta.to.shared.u64 t, %1; cvt.u32.u64 %0, t; }"
        : "=r"(a) : "l"(p));
    return a;
}
// 16B-atom xor swizzle within a 128B row: atom col c (0..7), row r
__device__ __forceinline__ uint32_t swz(uint32_t row, uint32_t c) {
    return row * 128u + ((c ^ (row & 7u)) << 4);
}

#define CP_ASYNC16(dst, src) \
    asm volatile("cp.async.cg.shared.global [%0], [%1], 16;" :: "r"(dst), "l"(src))
#define CP_COMMIT() asm volatile("cp.async.commit_group;")
#define CP_WAIT1()  asm volatile("cp.async.wait_group 1;")

#define LDM_X4(r0, r1, r2, r3, a) \
    asm volatile("ldmatrix.sync.aligned.m8n8.x4.shared.b16 {%0,%1,%2,%3}, [%4];" \
                 : "=r"(r0), "=r"(r1), "=r"(r2), "=r"(r3) : "r"(a))

#define MMA16816(d, a, b)                                                      \
    asm volatile(                                                              \
        "mma.sync.aligned.m16n8k16.row.col.f32.f16.f16.f32 "                   \
        "{%0,%1,%2,%3}, {%4,%5,%6,%7}, {%8,%9}, {%0,%1,%2,%3};"                \
        : "+f"((d)[0]), "+f"((d)[1]), "+f"((d)[2]), "+f"((d)[3])               \
        : "r"((a)[0]), "r"((a)[1]), "r"((a)[2]), "r"((a)[3]),                  \
          "r"((b)[0]), "r"((b)[1]))

// one ks-step: load fragments, run 16 MMAs
#define KS_STEP(ks)                                                            \
    do {                                                                       \
        uint32_t afr[4][4];                                                    \
        _Pragma("unroll")                                                      \
        for (int i = 0; i < 4; i++) {                                          \
            uint32_t addr = As + swz(a_row + i * 16, (ks) * 2 + a_kh);         \
            LDM_X4(afr[i][0], afr[i][1], afr[i][2], afr[i][3], addr);          \
        }                                                                      \
        uint32_t bfr[4][2];                                                    \
        _Pragma("unroll")                                                      \
        for (int jj = 0; jj < 2; jj++) {                                       \
            uint32_t addr = Bs + swz(b_row + jj * 16, (ks) * 2 + b_kh);        \
            uint32_t r0, r1, r2, r3;                                           \
            LDM_X4(r0, r1, r2, r3, addr);                                      \
            bfr[jj * 2][0] = r0;  bfr[jj * 2][1] = r1;                         \
            bfr[jj * 2 + 1][0] = r2; bfr[jj * 2 + 1][1] = r3;                  \
        }                                                                      \
        _Pragma("unroll")                                                      \
        for (int i = 0; i < 4; i++)                                            \
            _Pragma("unroll")                                                  \
            for (int j = 0; j < 4; j++)                                        \
                MMA16816(acc[i][j], afr[i], bfr[j]);                           \
    } while (0)

// ---------------------------------------------------------------------------
// fused prep: blocks [0, xblocks) convert x -> fp16 (8 floats/thread);
// the rest dequant W (one int4 = 4 packed bytes = 8 weights per thread).
// ---------------------------------------------------------------------------
__global__ __launch_bounds__(512)
void prep_kernel(const float* __restrict__ x,
                 const int* __restrict__ packed,
                 const float* __restrict__ mn,
                 const float* __restrict__ scale,
                 int xblocks) {
    if ((int)blockIdx.x < xblocks) {
        size_t t = (size_t)blockIdx.x * 512 + threadIdx.x;
        const float4* xv = reinterpret_cast<const float4*>(x);
        float4 v0 = __ldcs(xv + t * 2);
        float4 v1 = __ldcs(xv + t * 2 + 1);
        __half2 h0 = __floats2half2_rn(v0.x, v0.y);
        __half2 h1 = __floats2half2_rn(v0.z, v0.w);
        __half2 h2 = __floats2half2_rn(v1.x, v1.y);
        __half2 h3 = __floats2half2_rn(v1.z, v1.w);
        uint4 o;
        o.x = *reinterpret_cast<uint32_t*>(&h0);
        o.y = *reinterpret_cast<uint32_t*>(&h1);
        o.z = *reinterpret_cast<uint32_t*>(&h2);
        o.w = *reinterpret_cast<uint32_t*>(&h3);
        __stcs(reinterpret_cast<uint4*>(g_xh + t * 8), o);
    } else {
        uint32_t t = (blockIdx.x - xblocks) * 512 + threadIdx.x;
        uint32_t n   = t >> 9;             // 512 int4 per n row
        uint32_t rem = t & 511;
        uint32_t g   = rem >> 3;           // group
        uint32_t j4  = rem & 7;            // int4 within group (j = j4*4)
        int4 p = __ldcs(reinterpret_cast<const int4*>(packed) + t);
        float rcp = 1.0f / __ldg(scale + n * NUM_GROUPS + g);
        float mv  = __ldg(mn + n * NUM_GROUPS + g);
        int pv[4] = {p.x, p.y, p.z, p.w};
        __half hi[4], lo[4];
#pragma unroll
        for (int b = 0; b < 4; b++) {
            hi[b] = __float2half_rn((float)((pv[b] >> 4) & 0xF) * rcp + mv);
            lo[b] = __float2half_rn((float)(pv[b] & 0xF) * rcp + mv);
        }
        size_t base = (size_t)n * K_DIM + g * 64 + j4 * 4;
        __stcs(reinterpret_cast<uint2*>(g_wh + base),
               *reinterpret_cast<uint2*>(hi));
        __stcs(reinterpret_cast<uint2*>(g_wh + base + 32),
               *reinterpret_cast<uint2*>(lo));
    }
}

// ---------------------------------------------------------------------------
// GEMM: 256 threads (8 warps), warp tile 64x32, 3-stage pipeline, occ 2
// ---------------------------------------------------------------------------
__global__ __launch_bounds__(NT, 2)
void gemm_kernel(const float* __restrict__ bias, float* __restrict__ out) {
    extern __shared__ char smem[];
    const uint32_t sb = smem_u32(smem);
    const int tid = threadIdx.x;
    const int lane = tid & 31;
    const int wid = tid >> 5;
    const int warp_m = wid & 1;        // 2 warps along M
    const int warp_n = wid >> 1;       // 4 warps along N
    const int m_base = warp_m * 64;
    const int n_base = warp_n * 32;
    const int m0 = blockIdx.y * BM;
    const int n0 = blockIdx.x * BN;

    // cp.async slots as 32-bit byte offsets from scratch bases
    uint32_t ga_off[4], gb_off[4];
    uint32_t sa[4], sbo[4];
#pragma unroll
    for (int i = 0; i < 4; i++) {
        uint32_t idx = tid + i * NT;
        uint32_t r = idx >> 3, c = idx & 7;
        ga_off[i] = ((uint32_t)(m0 + r) * K_DIM + c * 8) * 2;
        sa[i]     = swz(r, c);
        gb_off[i] = ((uint32_t)(n0 + r) * K_DIM + c * 8) * 2;
        sbo[i]    = A_BYTES + swz(r, c);
    }
    const char* gxb = (const char*)g_xh;
    const char* gwb = (const char*)g_wh;

    float acc[4][4][4];
#pragma unroll
    for (int i = 0; i < 4; i++)
#pragma unroll
        for (int j = 0; j < 4; j++)
#pragma unroll
            for (int q = 0; q < 4; q++) acc[i][j][q] = 0.0f;

    // ldmatrix per-thread row components
    const uint32_t a_row = m_base + (lane & 15);       // + i*16
    const uint32_t a_kh  = (lane >> 4) & 1;
    const uint32_t b_row = n_base + (((lane >> 4) & 1) << 3) + (lane & 7); // + jj*16
    const uint32_t b_kh  = (lane >> 3) & 1;

    // ---- prologue: stages 0..1 ----
#pragma unroll
    for (int s = 0; s < STAGES - 1; s++) {
        uint32_t soff = sb + s * STAGE_BYTES;
        uint32_t koff = (uint32_t)s * BK * 2;   // 128 B per kt
#pragma unroll
        for (int i = 0; i < 4; i++) {
            CP_ASYNC16(soff + sa[i], gxb + ga_off[i] + koff);
            CP_ASYNC16(soff + sbo[i], gwb + gb_off[i] + koff);
        }
        CP_COMMIT();
    }

    int stage = 0;          // stage holding kt
#pragma unroll 2
    for (int kt = 0; kt < KT_COUNT; kt++) {
        CP_WAIT1();
        __syncthreads();

        uint32_t As = sb + stage * STAGE_BYTES;
        uint32_t Bs = As + A_BYTES;

        // prefetch target: stage freed at kt-1, data for kt+2
        const int pf = kt + STAGES - 1;
        int sp = stage + 2;
        if (sp >= STAGES) sp -= STAGES;
        const uint32_t pf_soff = sb + sp * STAGE_BYTES;
        const uint32_t pf_koff = (uint32_t)pf * BK * 2;
        stage++; if (stage >= STAGES) stage = 0;

        // ---- ks0 MMAs, then first half of prefetch ----
        KS_STEP(0);
        if (pf < KT_COUNT) {
#pragma unroll
            for (int i = 0; i < 2; i++) {
                CP_ASYNC16(pf_soff + sa[i], gxb + ga_off[i] + pf_koff);
                CP_ASYNC16(pf_soff + sbo[i], gwb + gb_off[i] + pf_koff);
            }
        }

        // ---- ks1 MMAs, then second half of prefetch + commit ----
        KS_STEP(1);
        if (pf < KT_COUNT) {
#pragma unroll
            for (int i = 2; i < 4; i++) {
                CP_ASYNC16(pf_soff + sa[i], gxb + ga_off[i] + pf_koff);
                CP_ASYNC16(pf_soff + sbo[i], gwb + gb_off[i] + pf_koff);
            }
        }
        CP_COMMIT();   // empty group when done keeps wait invariant

        // ---- ks2, ks3 ----
        KS_STEP(2);
        KS_STEP(3);
    }

    // ---- epilogue: bias + streaming stores ----
    const int tq = lane >> 2;          // row within 16
    const int tr = lane & 3;           // col pair
#pragma unroll
    for (int i = 0; i < 4; i++) {
        size_t mrow0 = (size_t)m0 + m_base + i * 16 + tq;
#pragma unroll
        for (int j = 0; j < 4; j++) {
            int ncol = n0 + n_base + j * 8 + tr * 2;
            float2 bv = __ldg(reinterpret_cast<const float2*>(bias + ncol));
            float2 v0 = {acc[i][j][0] + bv.x, acc[i][j][1] + bv.y};
            float2 v1 = {acc[i][j][2] + bv.x, acc[i][j][3] + bv.y};
            __stcs(reinterpret_cast<float2*>(out + mrow0 * N_DIM + ncol), v0);
            __stcs(reinterpret_cast<float2*>(out + (mrow0 + 8) * N_DIM + ncol), v1);
        }
    }
}

// ---------------------------------------------------------------------------
extern "C" void kernel_launch(void* const* d_in, const int* in_sizes, int n_in,
                              void* d_out, int out_size) {
    const float* x      = (const float*)d_in[0];
    const int*   packed = (const int*)d_in[1];
    const float* mn     = (const float*)d_in[2];
    const float* scale  = (const float*)d_in[3];
    const float* bias   = (const float*)d_in[4];
    float* out = (float*)d_out;

    const int M = in_sizes[0] / K_DIM;                 // 8192

    cudaFuncSetAttribute(gemm_kernel,
                         cudaFuncAttributeMaxDynamicSharedMemorySize, SMEM_TOTAL);

    const int xblocks = (int)(((size_t)M * K_DIM / 8) / 512);            // 8192
    const int wblocks = (N_DIM * NUM_GROUPS * 8) / 512;                  // 4096
    prep_kernel<<<xblocks + wblocks, 512>>>(x, packed, mn, scale, xblocks);

    dim3 grid(N_DIM / BN, M / BM);                     // (32, 64)
    gemm_kernel<<<grid, NT, SMEM_TOTAL>>>(bias, out);
}

// round 13
// speedup vs baseline: 1.0281x; 1.0281x over previous
#include <cuda_runtime.h>
#include <cuda_fp16.h>
#include <cstdint>

// ============================================================================
// CLinear: out[M,N] = x[M,K] @ dequant(W)[N,K]^T + bias
// M=8192, N=4096, K=4096. Base-compute_103-safe: mma.sync fp16 + cp.async.
// R13: R11 (best: 591.6us) with kt-loop unroll 3 == stage period, so stage
//      indices fold to compile-time constants in each unrolled copy.
// ============================================================================

#define K_DIM 4096
#define N_DIM 4096
#define NUM_GROUPS 64
#define M_MAX 8192

#define BM 128
#define BN 128
#define BK 64
#define KT_COUNT (K_DIM / BK)      // 64
#define STAGES 3
#define A_BYTES (BM * BK * 2)      // 16384
#define B_BYTES (BN * BK * 2)      // 16384
#define STAGE_BYTES (A_BYTES + B_BYTES)          // 32768
#define SMEM_TOTAL (STAGES * STAGE_BYTES)        // 98304 -> 2 CTAs/SM
#define NT 256

// fp16 scratch (device globals: the only legal scratch)
__device__ __half g_xh[(size_t)M_MAX * K_DIM];   // 64 MB
__device__ __half g_wh[(size_t)N_DIM * K_DIM];   // 32 MB

// ---------------------------------------------------------------------------
__device__ __forceinline__ uint32_t smem_u32(const void* p) {
    uint32_t a;
    asm("{ .reg .u64 t; cvta.to.shared.u64 t, %1; cvt.u32.u64 %0, t; }"
        : "=r"(a) : "l"(p));
    return a;
}
// 16B-atom xor swizzle within a 128B row: atom col c (0..7), row r
__device__ __forceinline__ uint32_t swz(uint32_t row, uint32_t c) {
    return row * 128u + ((c ^ (row & 7u)) << 4);
}

#define CP_ASYNC16(dst, src) \
    asm volatile("cp.async.cg.shared.global [%0], [%1], 16;" :: "r"(dst), "l"(src))
#define CP_COMMIT() asm volatile("cp.async.commit_group;")
#define CP_WAIT1()  asm volatile("cp.async.wait_group 1;")

#define LDM_X4(r0, r1, r2, r3, a) \
    asm volatile("ldmatrix.sync.aligned.m8n8.x4.shared.b16 {%0,%1,%2,%3}, [%4];" \
                 : "=r"(r0), "=r"(r1), "=r"(r2), "=r"(r3) : "r"(a))

#define MMA16816(d, a, b)                                                      \
    asm volatile(                                                              \
        "mma.sync.aligned.m16n8k16.row.col.f32.f16.f16.f32 "                   \
        "{%0,%1,%2,%3}, {%4,%5,%6,%7}, {%8,%9}, {%0,%1,%2,%3};"                \
        : "+f"((d)[0]), "+f"((d)[1]), "+f"((d)[2]), "+f"((d)[3])               \
        : "r"((a)[0]), "r"((a)[1]), "r"((a)[2]), "r"((a)[3]),                  \
          "r"((b)[0]), "r"((b)[1]))

// ---------------------------------------------------------------------------
// fused prep: blocks [0, xblocks) convert x -> fp16 (8 floats/thread);
// the rest dequant W (one int4 = 4 packed bytes = 8 weights per thread).
// ---------------------------------------------------------------------------
__global__ __launch_bounds__(512)
void prep_kernel(const float* __restrict__ x,
                 const int* __restrict__ packed,
                 const float* __restrict__ mn,
                 const float* __restrict__ scale,
                 int xblocks) {
    if ((int)blockIdx.x < xblocks) {
        size_t t = (size_t)blockIdx.x * 512 + threadIdx.x;
        const float4* xv = reinterpret_cast<const float4*>(x);
        float4 v0 = __ldcs(xv + t * 2);
        float4 v1 = __ldcs(xv + t * 2 + 1);
        __half2 h0 = __floats2half2_rn(v0.x, v0.y);
        __half2 h1 = __floats2half2_rn(v0.z, v0.w);
        __half2 h2 = __floats2half2_rn(v1.x, v1.y);
        __half2 h3 = __floats2half2_rn(v1.z, v1.w);
        uint4 o;
        o.x = *reinterpret_cast<uint32_t*>(&h0);
        o.y = *reinterpret_cast<uint32_t*>(&h1);
        o.z = *reinterpret_cast<uint32_t*>(&h2);
        o.w = *reinterpret_cast<uint32_t*>(&h3);
        __stcs(reinterpret_cast<uint4*>(g_xh + t * 8), o);
    } else {
        uint32_t t = (blockIdx.x - xblocks) * 512 + threadIdx.x;
        uint32_t n   = t >> 9;             // 512 int4 per n row
        uint32_t rem = t & 511;
        uint32_t g   = rem >> 3;           // group
        uint32_t j4  = rem & 7;            // int4 within group (j = j4*4)
        int4 p = __ldcs(reinterpret_cast<const int4*>(packed) + t);
        float rcp = 1.0f / __ldg(scale + n * NUM_GROUPS + g);
        float mv  = __ldg(mn + n * NUM_GROUPS + g);
        int pv[4] = {p.x, p.y, p.z, p.w};
        __half hi[4], lo[4];
#pragma unroll
        for (int b = 0; b < 4; b++) {
            hi[b] = __float2half_rn((float)((pv[b] >> 4) & 0xF) * rcp + mv);
            lo[b] = __float2half_rn((float)(pv[b] & 0xF) * rcp + mv);
        }
        size_t base = (size_t)n * K_DIM + g * 64 + j4 * 4;
        __stcs(reinterpret_cast<uint2*>(g_wh + base),
               *reinterpret_cast<uint2*>(hi));
        __stcs(reinterpret_cast<uint2*>(g_wh + base + 32),
               *reinterpret_cast<uint2*>(lo));
    }
}

// ---------------------------------------------------------------------------
// GEMM: 256 threads (8 warps), warp tile 64x32, 3-stage pipeline, occ 2
// ---------------------------------------------------------------------------
__global__ __launch_bounds__(NT, 2)
void gemm_kernel(const float* __restrict__ bias, float* __restrict__ out) {
    extern __shared__ char smem[];
    const uint32_t sb = smem_u32(smem);
    const int tid = threadIdx.x;
    const int lane = tid & 31;
    const int wid = tid >> 5;
    const int warp_m = wid & 1;        // 2 warps along M
    const int warp_n = wid >> 1;       // 4 warps along N
    const int m_base = warp_m * 64;
    const int n_base = warp_n * 32;
    const int m0 = blockIdx.y * BM;
    const int n0 = blockIdx.x * BN;

    // cp.async slots as 32-bit byte offsets from scratch bases
    uint32_t ga_off[4], gb_off[4];
    uint32_t sa[4], sbo[4];
#pragma unroll
    for (int i = 0; i < 4; i++) {
        uint32_t idx = tid + i * NT;
        uint32_t r = idx >> 3, c = idx & 7;
        ga_off[i] = ((uint32_t)(m0 + r) * K_DIM + c * 8) * 2;
        sa[i]     = swz(r, c);
        gb_off[i] = ((uint32_t)(n0 + r) * K_DIM + c * 8) * 2;
        sbo[i]    = A_BYTES + swz(r, c);
    }
    const char* gxb = (const char*)g_xh;
    const char* gwb = (const char*)g_wh;

    float acc[4][4][4];
#pragma unroll
    for (int i = 0; i < 4; i++)
#pragma unroll
        for (int j = 0; j < 4; j++)
#pragma unroll
            for (int q = 0; q < 4; q++) acc[i][j][q] = 0.0f;

    // ldmatrix per-thread row components
    const uint32_t a_row = m_base + (lane & 15);       // + i*16
    const uint32_t a_kh  = (lane >> 4) & 1;
    const uint32_t b_row = n_base + (((lane >> 4) & 1) << 3) + (lane & 7); // + jj*16
    const uint32_t b_kh  = (lane >> 3) & 1;

    // ---- prologue: stages 0..1 ----
#pragma unroll
    for (int s = 0; s < STAGES - 1; s++) {
        uint32_t soff = sb + s * STAGE_BYTES;
        uint32_t koff = (uint32_t)s * BK * 2;   // 128 B per kt
#pragma unroll
        for (int i = 0; i < 4; i++) {
            CP_ASYNC16(soff + sa[i], gxb + ga_off[i] + koff);
            CP_ASYNC16(soff + sbo[i], gwb + gb_off[i] + koff);
        }
        CP_COMMIT();
    }

    // kt loop: unroll 3 == stage period, so stage indices are compile-time
    // constants within each unrolled copy.
#pragma unroll 3
    for (int kt = 0; kt < KT_COUNT; kt++) {
        const int stage = kt % STAGES;
        CP_WAIT1();
        __syncthreads();

        uint32_t As = sb + stage * STAGE_BYTES;
        uint32_t Bs = As + A_BYTES;

        // ---- ks = 0: fragments + MMAs first so tensor work starts now ----
#pragma unroll
        for (int ks = 0; ks < 1; ks++) {
            uint32_t afr[4][4];
#pragma unroll
            for (int i = 0; i < 4; i++) {
                uint32_t addr = As + swz(a_row + i * 16, ks * 2 + a_kh);
                LDM_X4(afr[i][0], afr[i][1], afr[i][2], afr[i][3], addr);
            }
            uint32_t bfr[4][2];
#pragma unroll
            for (int jj = 0; jj < 2; jj++) {
                uint32_t addr = Bs + swz(b_row + jj * 16, ks * 2 + b_kh);
                uint32_t r0, r1, r2, r3;
                LDM_X4(r0, r1, r2, r3, addr);
                bfr[jj * 2][0] = r0;  bfr[jj * 2][1] = r1;
                bfr[jj * 2 + 1][0] = r2; bfr[jj * 2 + 1][1] = r3;
            }
#pragma unroll
            for (int i = 0; i < 4; i++)
#pragma unroll
                for (int j = 0; j < 4; j++)
                    MMA16816(acc[i][j], afr[i], bfr[j]);
        }

        // ---- prefetch kt+2 into the stage freed at kt-1 (after ks0) ----
        {
            int pf = kt + STAGES - 1;
            if (pf < KT_COUNT) {
                const int sp = (stage + 2) % STAGES;
                uint32_t soff = sb + sp * STAGE_BYTES;
                uint32_t koff = (uint32_t)pf * BK * 2;
#pragma unroll
                for (int i = 0; i < 4; i++) {
                    CP_ASYNC16(soff + sa[i], gxb + ga_off[i] + koff);
                    CP_ASYNC16(soff + sbo[i], gwb + gb_off[i] + koff);
                }
            }
            CP_COMMIT();   // empty group when done keeps wait invariant
        }

        // ---- ks = 1..3 ----
#pragma unroll
        for (int ks = 1; ks < 4; ks++) {
            uint32_t afr[4][4];
#pragma unroll
            for (int i = 0; i < 4; i++) {
                uint32_t addr = As + swz(a_row + i * 16, ks * 2 + a_kh);
                LDM_X4(afr[i][0], afr[i][1], afr[i][2], afr[i][3], addr);
            }
            uint32_t bfr[4][2];
#pragma unroll
            for (int jj = 0; jj < 2; jj++) {
                uint32_t addr = Bs + swz(b_row + jj * 16, ks * 2 + b_kh);
                uint32_t r0, r1, r2, r3;
                LDM_X4(r0, r1, r2, r3, addr);
                bfr[jj * 2][0] = r0;  bfr[jj * 2][1] = r1;
                bfr[jj * 2 + 1][0] = r2; bfr[jj * 2 + 1][1] = r3;
            }
#pragma unroll
            for (int i = 0; i < 4; i++)
#pragma unroll
                for (int j = 0; j < 4; j++)
                    MMA16816(acc[i][j], afr[i], bfr[j]);
        }
    }

    // ---- epilogue: bias + streaming stores ----
    const int tq = lane >> 2;          // row within 16
    const int tr = lane & 3;           // col pair
#pragma unroll
    for (int i = 0; i < 4; i++) {
        size_t mrow0 = (size_t)m0 + m_base + i * 16 + tq;
#pragma unroll
        for (int j = 0; j < 4; j++) {
            int ncol = n0 + n_base + j * 8 + tr * 2;
            float2 bv = __ldg(reinterpret_cast<const float2*>(bias + ncol));
            float2 v0 = {acc[i][j][0] + bv.x, acc[i][j][1] + bv.y};
            float2 v1 = {acc[i][j][2] + bv.x, acc[i][j][3] + bv.y};
            __stcs(reinterpret_cast<float2*>(out + mrow0 * N_DIM + ncol), v0);
            __stcs(reinterpret_cast<float2*>(out + (mrow0 + 8) * N_DIM + ncol), v1);
        }
    }
}

// ---------------------------------------------------------------------------
extern "C" void kernel_launch(void* const* d_in, const int* in_sizes, int n_in,
                              void* d_out, int out_size) {
    const float* x      = (const float*)d_in[0];
    const int*   packed = (const int*)d_in[1];
    const float* mn     = (const float*)d_in[2];
    const float* scale  = (const float*)d_in[3];
    const float* bias   = (const float*)d_in[4];
    float* out = (float*)d_out;

    const int M = in_sizes[0] / K_DIM;                 // 8192

    cudaFuncSetAttribute(gemm_kernel,
                         cudaFuncAttributeMaxDynamicSharedMemorySize, SMEM_TOTAL);

    const int xblocks = (int)(((size_t)M * K_DIM / 8) / 512);            // 8192
    const int wblocks = (N_DIM * NUM_GROUPS * 8) / 512;                  // 4096
    prep_kernel<<<xblocks + wblocks, 512>>>(x, packed, mn, scale, xblocks);

    dim3 grid(N_DIM / BN, M / BM);                     // (32, 64)
    gemm_kernel<<<grid, NT, SMEM_TOTAL>>>(bias, out);
}

// round 14
// speedup vs baseline: 1.0393x; 1.0108x over previous
#include <cuda_runtime.h>
#include <cuda_fp16.h>
#include <cstdint>

// ============================================================================
// CLinear: out[M,N] = x[M,K] @ dequant(W)[N,K]^T + bias
// M=8192, N=4096, K=4096. Base-compute_103-safe: mma.sync fp16 + cp.async.
// R14: 4 warps of 64x64 (square warp tile halves fragment duplication:
//      96KB -> 64KB smem reads per CTA per kt), 128 threads, occ 2 kept
//      (96KB smem, reg cap 256). Pipeline skeleton = validated R11/R13.
// ============================================================================

#define K_DIM 4096
#define N_DIM 4096
#define NUM_GROUPS 64
#define M_MAX 8192

#define BM 128
#define BN 128
#define BK 64
#define KT_COUNT (K_DIM / BK)      // 64
#define STAGES 3
#define A_BYTES (BM * BK * 2)      // 16384
#define B_BYTES (BN * BK * 2)      // 16384
#define STAGE_BYTES (A_BYTES + B_BYTES)          // 32768
#define SMEM_TOTAL (STAGES * STAGE_BYTES)        // 98304 -> 2 CTAs/SM
#define NT 128

// fp16 scratch (device globals: the only legal scratch)
__device__ __half g_xh[(size_t)M_MAX * K_DIM];   // 64 MB
__device__ __half g_wh[(size_t)N_DIM * K_DIM];   // 32 MB

// ---------------------------------------------------------------------------
__device__ __forceinline__ uint32_t smem_u32(const void* p) {
    uint32_t a;
    asm("{ .reg .u64 t; cvta.to.shared.u64 t, %1; cvt.u32.u64 %0, t; }"
        : "=r"(a) : "l"(p));
    return a;
}
// 16B-atom xor swizzle within a 128B row: atom col c (0..7), row r
__device__ __forceinline__ uint32_t swz(uint32_t row, uint32_t c) {
    return row * 128u + ((c ^ (row & 7u)) << 4);
}

#define CP_ASYNC16(dst, src) \
    asm volatile("cp.async.cg.shared.global [%0], [%1], 16;" :: "r"(dst), "l"(src))
#define CP_COMMIT() asm volatile("cp.async.commit_group;")
#define CP_WAIT1()  asm volatile("cp.async.wait_group 1;")

#define LDM_X4(r0, r1, r2, r3, a) \
    asm volatile("ldmatrix.sync.aligned.m8n8.x4.shared.b16 {%0,%1,%2,%3}, [%4];" \
                 : "=r"(r0), "=r"(r1), "=r"(r2), "=r"(r3) : "r"(a))

#define MMA16816(d, a, b)                                                      \
    asm volatile(                                                              \
        "mma.sync.aligned.m16n8k16.row.col.f32.f16.f16.f32 "                   \
        "{%0,%1,%2,%3}, {%4,%5,%6,%7}, {%8,%9}, {%0,%1,%2,%3};"                \
        : "+f"((d)[0]), "+f"((d)[1]), "+f"((d)[2]), "+f"((d)[3])               \
        : "r"((a)[0]), "r"((a)[1]), "r"((a)[2]), "r"((a)[3]),                  \
          "r"((b)[0]), "r"((b)[1]))

// ---------------------------------------------------------------------------
// fused prep: blocks [0, xblocks) convert x -> fp16 (8 floats/thread);
// the rest dequant W (one int4 = 4 packed bytes = 8 weights per thread).
// ---------------------------------------------------------------------------
__global__ __launch_bounds__(512)
void prep_kernel(const float* __restrict__ x,
                 const int* __restrict__ packed,
                 const float* __restrict__ mn,
                 const float* __restrict__ scale,
                 int xblocks) {
    if ((int)blockIdx.x < xblocks) {
        size_t t = (size_t)blockIdx.x * 512 + threadIdx.x;
        const float4* xv = reinterpret_cast<const float4*>(x);
        float4 v0 = __ldcs(xv + t * 2);
        float4 v1 = __ldcs(xv + t * 2 + 1);
        __half2 h0 = __floats2half2_rn(v0.x, v0.y);
        __half2 h1 = __floats2half2_rn(v0.z, v0.w);
        __half2 h2 = __floats2half2_rn(v1.x, v1.y);
        __half2 h3 = __floats2half2_rn(v1.z, v1.w);
        uint4 o;
        o.x = *reinterpret_cast<uint32_t*>(&h0);
        o.y = *reinterpret_cast<uint32_t*>(&h1);
        o.z = *reinterpret_cast<uint32_t*>(&h2);
        o.w = *reinterpret_cast<uint32_t*>(&h3);
        __stcs(reinterpret_cast<uint4*>(g_xh + t * 8), o);
    } else {
        uint32_t t = (blockIdx.x - xblocks) * 512 + threadIdx.x;
        uint32_t n   = t >> 9;             // 512 int4 per n row
        uint32_t rem = t & 511;
        uint32_t g   = rem >> 3;           // group
        uint32_t j4  = rem & 7;            // int4 within group (j = j4*4)
        int4 p = __ldcs(reinterpret_cast<const int4*>(packed) + t);
        float rcp = 1.0f / __ldg(scale + n * NUM_GROUPS + g);
        float mv  = __ldg(mn + n * NUM_GROUPS + g);
        int pv[4] = {p.x, p.y, p.z, p.w};
        __half hi[4], lo[4];
#pragma unroll
        for (int b = 0; b < 4; b++) {
            hi[b] = __float2half_rn((float)((pv[b] >> 4) & 0xF) * rcp + mv);
            lo[b] = __float2half_rn((float)(pv[b] & 0xF) * rcp + mv);
        }
        size_t base = (size_t)n * K_DIM + g * 64 + j4 * 4;
        __stcs(reinterpret_cast<uint2*>(g_wh + base),
               *reinterpret_cast<uint2*>(hi));
        __stcs(reinterpret_cast<uint2*>(g_wh + base + 32),
               *reinterpret_cast<uint2*>(lo));
    }
}

// ---------------------------------------------------------------------------
// GEMM: 128 threads (4 warps of 64x64), 3-stage pipeline, occ 2
// ---------------------------------------------------------------------------
__global__ __launch_bounds__(NT, 2)
void gemm_kernel(const float* __restrict__ bias, float* __restrict__ out) {
    extern __shared__ char smem[];
    const uint32_t sb = smem_u32(smem);
    const int tid = threadIdx.x;
    const int lane = tid & 31;
    const int wid = tid >> 5;
    const int warp_m = wid & 1;        // 2 warps along M
    const int warp_n = wid >> 1;       // 2 warps along N
    const int m_base = warp_m * 64;
    const int n_base = warp_n * 64;
    const int m0 = blockIdx.y * BM;
    const int n0 = blockIdx.x * BN;

    // cp.async slots as 32-bit byte offsets from scratch bases
    // A: 1024 atoms -> 8/thread.  B: 1024 atoms -> 8/thread.
    uint32_t ga_off[8], gb_off[8];
    uint32_t sa[8], sbo[8];
#pragma unroll
    for (int i = 0; i < 8; i++) {
        uint32_t idx = tid + i * NT;
        uint32_t r = idx >> 3, c = idx & 7;
        ga_off[i] = ((uint32_t)(m0 + r) * K_DIM + c * 8) * 2;
        sa[i]     = swz(r, c);
        gb_off[i] = ((uint32_t)(n0 + r) * K_DIM + c * 8) * 2;
        sbo[i]    = A_BYTES + swz(r, c);
    }
    const char* gxb = (const char*)g_xh;
    const char* gwb = (const char*)g_wh;

    float acc[4][8][4];
#pragma unroll
    for (int i = 0; i < 4; i++)
#pragma unroll
        for (int j = 0; j < 8; j++)
#pragma unroll
            for (int q = 0; q < 4; q++) acc[i][j][q] = 0.0f;

    // ldmatrix per-thread row components
    const uint32_t a_row = m_base + (lane & 15);       // + i*16
    const uint32_t a_kh  = (lane >> 4) & 1;
    const uint32_t b_row = n_base + (((lane >> 4) & 1) << 3) + (lane & 7); // + jj*16
    const uint32_t b_kh  = (lane >> 3) & 1;

    // ---- prologue: stages 0..1 ----
#pragma unroll
    for (int s = 0; s < STAGES - 1; s++) {
        uint32_t soff = sb + s * STAGE_BYTES;
        uint32_t koff = (uint32_t)s * BK * 2;   // 128 B per kt
#pragma unroll
        for (int i = 0; i < 8; i++) {
            CP_ASYNC16(soff + sa[i], gxb + ga_off[i] + koff);
            CP_ASYNC16(soff + sbo[i], gwb + gb_off[i] + koff);
        }
        CP_COMMIT();
    }

    // kt loop: unroll 3 == stage period, stage indices compile-time constant
#pragma unroll 3
    for (int kt = 0; kt < KT_COUNT; kt++) {
        const int stage = kt % STAGES;
        CP_WAIT1();
        __syncthreads();

        uint32_t As = sb + stage * STAGE_BYTES;
        uint32_t Bs = As + A_BYTES;

        // ---- ks = 0: fragments + MMAs first so tensor work starts now ----
#pragma unroll
        for (int ks = 0; ks < 1; ks++) {
            uint32_t afr[4][4];
#pragma unroll
            for (int i = 0; i < 4; i++) {
                uint32_t addr = As + swz(a_row + i * 16, ks * 2 + a_kh);
                LDM_X4(afr[i][0], afr[i][1], afr[i][2], afr[i][3], addr);
            }
            uint32_t bfr[8][2];
#pragma unroll
            for (int jj = 0; jj < 4; jj++) {
                uint32_t addr = Bs + swz(b_row + jj * 16, ks * 2 + b_kh);
                uint32_t r0, r1, r2, r3;
                LDM_X4(r0, r1, r2, r3, addr);
                bfr[jj * 2][0] = r0;  bfr[jj * 2][1] = r1;
                bfr[jj * 2 + 1][0] = r2; bfr[jj * 2 + 1][1] = r3;
            }
#pragma unroll
            for (int i = 0; i < 4; i++)
#pragma unroll
                for (int j = 0; j < 8; j++)
                    MMA16816(acc[i][j], afr[i], bfr[j]);
        }

        // ---- prefetch kt+2 into the stage freed at kt-1 (after ks0) ----
        {
            int pf = kt + STAGES - 1;
            if (pf < KT_COUNT) {
                const int sp = (stage + 2) % STAGES;
                uint32_t soff = sb + sp * STAGE_BYTES;
                uint32_t koff = (uint32_t)pf * BK * 2;
#pragma unroll
                for (int i = 0; i < 8; i++) {
                    CP_ASYNC16(soff + sa[i], gxb + ga_off[i] + koff);
                    CP_ASYNC16(soff + sbo[i], gwb + gb_off[i] + koff);
                }
            }
            CP_COMMIT();   // empty group when done keeps wait invariant
        }

        // ---- ks = 1..3 ----
#pragma unroll
        for (int ks = 1; ks < 4; ks++) {
            uint32_t afr[4][4];
#pragma unroll
            for (int i = 0; i < 4; i++) {
                uint32_t addr = As + swz(a_row + i * 16, ks * 2 + a_kh);
                LDM_X4(afr[i][0], afr[i][1], afr[i][2], afr[i][3], addr);
            }
            uint32_t bfr[8][2];
#pragma unroll
            for (int jj = 0; jj < 4; jj++) {
                uint32_t addr = Bs + swz(b_row + jj * 16, ks * 2 + b_kh);
                uint32_t r0, r1, r2, r3;
                LDM_X4(r0, r1, r2, r3, addr);
                bfr[jj * 2][0] = r0;  bfr[jj * 2][1] = r1;
                bfr[jj * 2 + 1][0] = r2; bfr[jj * 2 + 1][1] = r3;
            }
#pragma unroll
            for (int i = 0; i < 4; i++)
#pragma unroll
                for (int j = 0; j < 8; j++)
                    MMA16816(acc[i][j], afr[i], bfr[j]);
        }
    }

    // ---- epilogue: bias + streaming stores ----
    const int tq = lane >> 2;          // row within 16
    const int tr = lane & 3;           // col pair
#pragma unroll
    for (int i = 0; i < 4; i++) {
        size_t mrow0 = (size_t)m0 + m_base + i * 16 + tq;
#pragma unroll
        for (int j = 0; j < 8; j++) {
            int ncol = n0 + n_base + j * 8 + tr * 2;
            float2 bv = __ldg(reinterpret_cast<const float2*>(bias + ncol));
            float2 v0 = {acc[i][j][0] + bv.x, acc[i][j][1] + bv.y};
            float2 v1 = {acc[i][j][2] + bv.x, acc[i][j][3] + bv.y};
            __stcs(reinterpret_cast<float2*>(out + mrow0 * N_DIM + ncol), v0);
            __stcs(reinterpret_cast<float2*>(out + (mrow0 + 8) * N_DIM + ncol), v1);
        }
    }
}

// ---------------------------------------------------------------------------
extern "C" void kernel_launch(void* const* d_in, const int* in_sizes, int n_in,
                              void* d_out, int out_size) {
    const float* x      = (const float*)d_in[0];
    const int*   packed = (const int*)d_in[1];
    const float* mn     = (const float*)d_in[2];
    const float* scale  = (const float*)d_in[3];
    const float* bias   = (const float*)d_in[4];
    float* out = (float*)d_out;

    const int M = in_sizes[0] / K_DIM;                 // 8192

    cudaFuncSetAttribute(gemm_kernel,
                         cudaFuncAttributeMaxDynamicSharedMemorySize, SMEM_TOTAL);

    const int xblocks = (int)(((size_t)M * K_DIM / 8) / 512);            // 8192
    const int wblocks = (N_DIM * NUM_GROUPS * 8) / 512;                  // 4096
    prep_kernel<<<xblocks + wblocks, 512>>>(x, packed, mn, scale, xblocks);

    dim3 grid(N_DIM / BN, M / BM);                     // (32, 64)
    gemm_kernel<<<grid, NT, SMEM_TOTAL>>>(bias, out);
}

// round 15
// speedup vs baseline: 1.0421x; 1.0027x over previous
#include <cuda_runtime.h>
#include <cuda_fp16.h>
#include <cstdint>

// ============================================================================
// CLinear: out[M,N] = x[M,K] @ dequant(W)[N,K]^T + bias
// M=8192, N=4096, K=4096. Base-compute_103-safe: mma.sync fp16 + cp.async.
// R15: GEMM identical to R14 (best: 543.7us GEMM; 4 warps 64x64, occ 2).
//      Prep widened: x 16 floats/thread, W 2xint4/thread (same-group pair,
//      one scale/mn load per 16 weights, 2x16B stores).
// ============================================================================

#define K_DIM 4096
#define N_DIM 4096
#define NUM_GROUPS 64
#define M_MAX 8192

#define BM 128
#define BN 128
#define BK 64
#define KT_COUNT (K_DIM / BK)      // 64
#define STAGES 3
#define A_BYTES (BM * BK * 2)      // 16384
#define B_BYTES (BN * BK * 2)      // 16384
#define STAGE_BYTES (A_BYTES + B_BYTES)          // 32768
#define SMEM_TOTAL (STAGES * STAGE_BYTES)        // 98304 -> 2 CTAs/SM
#define NT 128

// fp16 scratch (device globals: the only legal scratch)
__device__ __half g_xh[(size_t)M_MAX * K_DIM];   // 64 MB
__device__ __half g_wh[(size_t)N_DIM * K_DIM];   // 32 MB

// ---------------------------------------------------------------------------
__device__ __forceinline__ uint32_t smem_u32(const void* p) {
    uint32_t a;
    asm("{ .reg .u64 t; cvta.to.shared.u64 t, %1; cvt.u32.u64 %0, t; }"
        : "=r"(a) : "l"(p));
    return a;
}
// 16B-atom xor swizzle within a 128B row: atom col c (0..7), row r
__device__ __forceinline__ uint32_t swz(uint32_t row, uint32_t c) {
    return row * 128u + ((c ^ (row & 7u)) << 4);
}

#define CP_ASYNC16(dst, src) \
    asm volatile("cp.async.cg.shared.global [%0], [%1], 16;" :: "r"(dst), "l"(src))
#define CP_COMMIT() asm volatile("cp.async.commit_group;")
#define CP_WAIT1()  asm volatile("cp.async.wait_group 1;")

#define LDM_X4(r0, r1, r2, r3, a) \
    asm volatile("ldmatrix.sync.aligned.m8n8.x4.shared.b16 {%0,%1,%2,%3}, [%4];" \
                 : "=r"(r0), "=r"(r1), "=r"(r2), "=r"(r3) : "r"(a))

#define MMA16816(d, a, b)                                                      \
    asm volatile(                                                              \
        "mma.sync.aligned.m16n8k16.row.col.f32.f16.f16.f32 "                   \
        "{%0,%1,%2,%3}, {%4,%5,%6,%7}, {%8,%9}, {%0,%1,%2,%3};"                \
        : "+f"((d)[0]), "+f"((d)[1]), "+f"((d)[2]), "+f"((d)[3])               \
        : "r"((a)[0]), "r"((a)[1]), "r"((a)[2]), "r"((a)[3]),                  \
          "r"((b)[0]), "r"((b)[1]))

// ---------------------------------------------------------------------------
// fused prep: blocks [0, xblocks) convert x -> fp16 (16 floats/thread);
// the rest dequant W (2 consecutive int4 = 16 weights per thread).
// ---------------------------------------------------------------------------
__global__ __launch_bounds__(512)
void prep_kernel(const float* __restrict__ x,
                 const int* __restrict__ packed,
                 const float* __restrict__ mn,
                 const float* __restrict__ scale,
                 int xblocks) {
    if ((int)blockIdx.x < xblocks) {
        // x path: 4 float4 in -> 2 uint4 (16 fp16) out
        size_t t = (size_t)blockIdx.x * 512 + threadIdx.x;
        const float4* xv = reinterpret_cast<const float4*>(x);
        float4 v0 = __ldcs(xv + t * 4);
        float4 v1 = __ldcs(xv + t * 4 + 1);
        float4 v2 = __ldcs(xv + t * 4 + 2);
        float4 v3 = __ldcs(xv + t * 4 + 3);
        __half2 h0 = __floats2half2_rn(v0.x, v0.y);
        __half2 h1 = __floats2half2_rn(v0.z, v0.w);
        __half2 h2 = __floats2half2_rn(v1.x, v1.y);
        __half2 h3 = __floats2half2_rn(v1.z, v1.w);
        __half2 h4 = __floats2half2_rn(v2.x, v2.y);
        __half2 h5 = __floats2half2_rn(v2.z, v2.w);
        __half2 h6 = __floats2half2_rn(v3.x, v3.y);
        __half2 h7 = __floats2half2_rn(v3.z, v3.w);
        uint4 o0, o1;
        o0.x = *reinterpret_cast<uint32_t*>(&h0);
        o0.y = *reinterpret_cast<uint32_t*>(&h1);
        o0.z = *reinterpret_cast<uint32_t*>(&h2);
        o0.w = *reinterpret_cast<uint32_t*>(&h3);
        o1.x = *reinterpret_cast<uint32_t*>(&h4);
        o1.y = *reinterpret_cast<uint32_t*>(&h5);
        o1.z = *reinterpret_cast<uint32_t*>(&h6);
        o1.w = *reinterpret_cast<uint32_t*>(&h7);
        __stcs(reinterpret_cast<uint4*>(g_xh + t * 16), o0);
        __stcs(reinterpret_cast<uint4*>(g_xh + t * 16 + 8), o1);
    } else {
        // W path: 2 consecutive int4 (even index => same quant group).
        // hi nibbles of the 8 ints cover k = g*64 + j4*4 .. +7 (contiguous),
        // lo nibbles the same +32.
        uint32_t t  = (blockIdx.x - xblocks) * 512 + threadIdx.x;
        uint32_t i0 = t * 2;               // first int4 index
        uint32_t n   = i0 >> 9;            // 512 int4 per n row
        uint32_t rem = i0 & 511;
        uint32_t g   = rem >> 3;           // group
        uint32_t j4  = rem & 7;            // even: pair stays in-group
        const int4* pk = reinterpret_cast<const int4*>(packed);
        int4 p0 = __ldcs(pk + i0);
        int4 p1 = __ldcs(pk + i0 + 1);
        float rcp = 1.0f / __ldg(scale + n * NUM_GROUPS + g);
        float mv  = __ldg(mn + n * NUM_GROUPS + g);
        int pv[8] = {p0.x, p0.y, p0.z, p0.w, p1.x, p1.y, p1.z, p1.w};
        __half hi[8], lo[8];
#pragma unroll
        for (int b = 0; b < 8; b++) {
            hi[b] = __float2half_rn((float)((pv[b] >> 4) & 0xF) * rcp + mv);
            lo[b] = __float2half_rn((float)(pv[b] & 0xF) * rcp + mv);
        }
        size_t base = (size_t)n * K_DIM + g * 64 + j4 * 4;   // 16B-aligned (j4 even)
        __stcs(reinterpret_cast<uint4*>(g_wh + base),
               *reinterpret_cast<uint4*>(hi));
        __stcs(reinterpret_cast<uint4*>(g_wh + base + 32),
               *reinterpret_cast<uint4*>(lo));
    }
}

// ---------------------------------------------------------------------------
// GEMM: 128 threads (4 warps of 64x64), 3-stage pipeline, occ 2  (R14 verbatim)
// ---------------------------------------------------------------------------
__global__ __launch_bounds__(NT, 2)
void gemm_kernel(const float* __restrict__ bias, float* __restrict__ out) {
    extern __shared__ char smem[];
    const uint32_t sb = smem_u32(smem);
    const int tid = threadIdx.x;
    const int lane = tid & 31;
    const int wid = tid >> 5;
    const int warp_m = wid & 1;        // 2 warps along M
    const int warp_n = wid >> 1;       // 2 warps along N
    const int m_base = warp_m * 64;
    const int n_base = warp_n * 64;
    const int m0 = blockIdx.y * BM;
    const int n0 = blockIdx.x * BN;

    // cp.async slots as 32-bit byte offsets from scratch bases
    uint32_t ga_off[8], gb_off[8];
    uint32_t sa[8], sbo[8];
#pragma unroll
    for (int i = 0; i < 8; i++) {
        uint32_t idx = tid + i * NT;
        uint32_t r = idx >> 3, c = idx & 7;
        ga_off[i] = ((uint32_t)(m0 + r) * K_DIM + c * 8) * 2;
        sa[i]     = swz(r, c);
        gb_off[i] = ((uint32_t)(n0 + r) * K_DIM + c * 8) * 2;
        sbo[i]    = A_BYTES + swz(r, c);
    }
    const char* gxb = (const char*)g_xh;
    const char* gwb = (const char*)g_wh;

    float acc[4][8][4];
#pragma unroll
    for (int i = 0; i < 4; i++)
#pragma unroll
        for (int j = 0; j < 8; j++)
#pragma unroll
            for (int q = 0; q < 4; q++) acc[i][j][q] = 0.0f;

    // ldmatrix per-thread row components
    const uint32_t a_row = m_base + (lane & 15);       // + i*16
    const uint32_t a_kh  = (lane >> 4) & 1;
    const uint32_t b_row = n_base + (((lane >> 4) & 1) << 3) + (lane & 7); // + jj*16
    const uint32_t b_kh  = (lane >> 3) & 1;

    // ---- prologue: stages 0..1 ----
#pragma unroll
    for (int s = 0; s < STAGES - 1; s++) {
        uint32_t soff = sb + s * STAGE_BYTES;
        uint32_t koff = (uint32_t)s * BK * 2;   // 128 B per kt
#pragma unroll
        for (int i = 0; i < 8; i++) {
            CP_ASYNC16(soff + sa[i], gxb + ga_off[i] + koff);
            CP_ASYNC16(soff + sbo[i], gwb + gb_off[i] + koff);
        }
        CP_COMMIT();
    }

    // kt loop: unroll 3 == stage period, stage indices compile-time constant
#pragma unroll 3
    for (int kt = 0; kt < KT_COUNT; kt++) {
        const int stage = kt % STAGES;
        CP_WAIT1();
        __syncthreads();

        uint32_t As = sb + stage * STAGE_BYTES;
        uint32_t Bs = As + A_BYTES;

        // ---- ks = 0: fragments + MMAs first so tensor work starts now ----
#pragma unroll
        for (int ks = 0; ks < 1; ks++) {
            uint32_t afr[4][4];
#pragma unroll
            for (int i = 0; i < 4; i++) {
                uint32_t addr = As + swz(a_row + i * 16, ks * 2 + a_kh);
                LDM_X4(afr[i][0], afr[i][1], afr[i][2], afr[i][3], addr);
            }
            uint32_t bfr[8][2];
#pragma unroll
            for (int jj = 0; jj < 4; jj++) {
                uint32_t addr = Bs + swz(b_row + jj * 16, ks * 2 + b_kh);
                uint32_t r0, r1, r2, r3;
                LDM_X4(r0, r1, r2, r3, addr);
                bfr[jj * 2][0] = r0;  bfr[jj * 2][1] = r1;
                bfr[jj * 2 + 1][0] = r2; bfr[jj * 2 + 1][1] = r3;
            }
#pragma unroll
            for (int i = 0; i < 4; i++)
#pragma unroll
                for (int j = 0; j < 8; j++)
                    MMA16816(acc[i][j], afr[i], bfr[j]);
        }

        // ---- prefetch kt+2 into the stage freed at kt-1 (after ks0) ----
        {
            int pf = kt + STAGES - 1;
            if (pf < KT_COUNT) {
                const int sp = (stage + 2) % STAGES;
                uint32_t soff = sb + sp * STAGE_BYTES;
                uint32_t koff = (uint32_t)pf * BK * 2;
#pragma unroll
                for (int i = 0; i < 8; i++) {
                    CP_ASYNC16(soff + sa[i], gxb + ga_off[i] + koff);
                    CP_ASYNC16(soff + sbo[i], gwb + gb_off[i] + koff);
                }
            }
            CP_COMMIT();   // empty group when done keeps wait invariant
        }

        // ---- ks = 1..3 ----
#pragma unroll
        for (int ks = 1; ks < 4; ks++) {
            uint32_t afr[4][4];
#pragma unroll
            for (int i = 0; i < 4; i++) {
                uint32_t addr = As + swz(a_row + i * 16, ks * 2 + a_kh);
                LDM_X4(afr[i][0], afr[i][1], afr[i][2], afr[i][3], addr);
            }
            uint32_t bfr[8][2];
#pragma unroll
            for (int jj = 0; jj < 4; jj++) {
                uint32_t addr = Bs + swz(b_row + jj * 16, ks * 2 + b_kh);
                uint32_t r0, r1, r2, r3;
                LDM_X4(r0, r1, r2, r3, addr);
                bfr[jj * 2][0] = r0;  bfr[jj * 2][1] = r1;
                bfr[jj * 2 + 1][0] = r2; bfr[jj * 2 + 1][1] = r3;
            }
#pragma unroll
            for (int i = 0; i < 4; i++)
#pragma unroll
                for (int j = 0; j < 8; j++)
                    MMA16816(acc[i][j], afr[i], bfr[j]);
        }
    }

    // ---- epilogue: bias + streaming stores ----
    const int tq = lane >> 2;          // row within 16
    const int tr = lane & 3;           // col pair
#pragma unroll
    for (int i = 0; i < 4; i++) {
        size_t mrow0 = (size_t)m0 + m_base + i * 16 + tq;
#pragma unroll
        for (int j = 0; j < 8; j++) {
            int ncol = n0 + n_base + j * 8 + tr * 2;
            float2 bv = __ldg(reinterpret_cast<const float2*>(bias + ncol));
            float2 v0 = {acc[i][j][0] + bv.x, acc[i][j][1] + bv.y};
            float2 v1 = {acc[i][j][2] + bv.x, acc[i][j][3] + bv.y};
            __stcs(reinterpret_cast<float2*>(out + mrow0 * N_DIM + ncol), v0);
            __stcs(reinterpret_cast<float2*>(out + (mrow0 + 8) * N_DIM + ncol), v1);
        }
    }
}

// ---------------------------------------------------------------------------
extern "C" void kernel_launch(void* const* d_in, const int* in_sizes, int n_in,
                              void* d_out, int out_size) {
    const float* x      = (const float*)d_in[0];
    const int*   packed = (const int*)d_in[1];
    const float* mn     = (const float*)d_in[2];
    const float* scale  = (const float*)d_in[3];
    const float* bias   = (const float*)d_in[4];
    float* out = (float*)d_out;

    const int M = in_sizes[0] / K_DIM;                 // 8192

    cudaFuncSetAttribute(gemm_kernel,
                         cudaFuncAttributeMaxDynamicSharedMemorySize, SMEM_TOTAL);

    const int xblocks = (int)(((size_t)M * K_DIM / 16) / 512);           // 4096
    const int wblocks = (N_DIM * 512 / 2) / 512;                         // 2048
    prep_kernel<<<xblocks + wblocks, 512>>>(x, packed, mn, scale, xblocks);

    dim3 grid(N_DIM / BN, M / BM);                     // (32, 64)
    gemm_kernel<<<grid, NT, SMEM_TOTAL>>>(bias, out);
}

// round 16
// speedup vs baseline: 1.0494x; 1.0070x over previous
#include <cuda_runtime.h>
#include <cuda_fp16.h>
#include <cstdint>

// ============================================================================
// CLinear: out[M,N] = x[M,K] @ dequant(W)[N,K]^T + bias
// M=8192, N=4096, K=4096. Base-compute_103-safe: mma.sync fp16 + cp.async.
// R16: R15 (best: 582.1us) + manual fragment double-buffering across ks,
//      viable now that 128-thread/occ-2 gives a 255-reg cap (R10's failure
//      was the 128-reg cap at 256 threads). Prefetch stays post-ks0-MMA.
// ============================================================================

#define K_DIM 4096
#define N_DIM 4096
#define NUM_GROUPS 64
#define M_MAX 8192

#define BM 128
#define BN 128
#define BK 64
#define KT_COUNT (K_DIM / BK)      // 64
#define STAGES 3
#define A_BYTES (BM * BK * 2)      // 16384
#define B_BYTES (BN * BK * 2)      // 16384
#define STAGE_BYTES (A_BYTES + B_BYTES)          // 32768
#define SMEM_TOTAL (STAGES * STAGE_BYTES)        // 98304 -> 2 CTAs/SM
#define NT 128

// fp16 scratch (device globals: the only legal scratch)
__device__ __half g_xh[(size_t)M_MAX * K_DIM];   // 64 MB
__device__ __half g_wh[(size_t)N_DIM * K_DIM];   // 32 MB

// ---------------------------------------------------------------------------
__device__ __forceinline__ uint32_t smem_u32(const void* p) {
    uint32_t a;
    asm("{ .reg .u64 t; cvta.to.shared.u64 t, %1; cvt.u32.u64 %0, t; }"
        : "=r"(a) : "l"(p));
    return a;
}
// 16B-atom xor swizzle within a 128B row: atom col c (0..7), row r
__device__ __forceinline__ uint32_t swz(uint32_t row, uint32_t c) {
    return row * 128u + ((c ^ (row & 7u)) << 4);
}

#define CP_ASYNC16(dst, src) \
    asm volatile("cp.async.cg.shared.global [%0], [%1], 16;" :: "r"(dst), "l"(src))
#define CP_COMMIT() asm volatile("cp.async.commit_group;")
#define CP_WAIT1()  asm volatile("cp.async.wait_group 1;")

#define LDM_X4(r0, r1, r2, r3, a) \
    asm volatile("ldmatrix.sync.aligned.m8n8.x4.shared.b16 {%0,%1,%2,%3}, [%4];" \
                 : "=r"(r0), "=r"(r1), "=r"(r2), "=r"(r3) : "r"(a))

#define MMA16816(d, a, b)                                                      \
    asm volatile(                                                              \
        "mma.sync.aligned.m16n8k16.row.col.f32.f16.f16.f32 "                   \
        "{%0,%1,%2,%3}, {%4,%5,%6,%7}, {%8,%9}, {%0,%1,%2,%3};"                \
        : "+f"((d)[0]), "+f"((d)[1]), "+f"((d)[2]), "+f"((d)[3])               \
        : "r"((a)[0]), "r"((a)[1]), "r"((a)[2]), "r"((a)[3]),                  \
          "r"((b)[0]), "r"((b)[1]))

// fragment load for one ks into buffer slot b
#define LOAD_FRAGS(ks, b)                                                      \
    do {                                                                       \
        _Pragma("unroll")                                                      \
        for (int i = 0; i < 4; i++) {                                          \
            uint32_t addr = As + swz(a_row + i * 16, (ks) * 2 + a_kh);         \
            LDM_X4(afr[b][i][0], afr[b][i][1], afr[b][i][2], afr[b][i][3], addr); \
        }                                                                      \
        _Pragma("unroll")                                                      \
        for (int jj = 0; jj < 4; jj++) {                                       \
            uint32_t addr = Bs + swz(b_row + jj * 16, (ks) * 2 + b_kh);        \
            uint32_t r0, r1, r2, r3;                                           \
            LDM_X4(r0, r1, r2, r3, addr);                                      \
            bfr[b][jj * 2][0] = r0;     bfr[b][jj * 2][1] = r1;                \
            bfr[b][jj * 2 + 1][0] = r2; bfr[b][jj * 2 + 1][1] = r3;            \
        }                                                                      \
    } while (0)

// ---------------------------------------------------------------------------
// fused prep: blocks [0, xblocks) convert x -> fp16 (16 floats/thread);
// the rest dequant W (2 consecutive int4 = 16 weights per thread).
// ---------------------------------------------------------------------------
__global__ __launch_bounds__(512)
void prep_kernel(const float* __restrict__ x,
                 const int* __restrict__ packed,
                 const float* __restrict__ mn,
                 const float* __restrict__ scale,
                 int xblocks) {
    if ((int)blockIdx.x < xblocks) {
        // x path: 4 float4 in -> 2 uint4 (16 fp16) out
        size_t t = (size_t)blockIdx.x * 512 + threadIdx.x;
        const float4* xv = reinterpret_cast<const float4*>(x);
        float4 v0 = __ldcs(xv + t * 4);
        float4 v1 = __ldcs(xv + t * 4 + 1);
        float4 v2 = __ldcs(xv + t * 4 + 2);
        float4 v3 = __ldcs(xv + t * 4 + 3);
        __half2 h0 = __floats2half2_rn(v0.x, v0.y);
        __half2 h1 = __floats2half2_rn(v0.z, v0.w);
        __half2 h2 = __floats2half2_rn(v1.x, v1.y);
        __half2 h3 = __floats2half2_rn(v1.z, v1.w);
        __half2 h4 = __floats2half2_rn(v2.x, v2.y);
        __half2 h5 = __floats2half2_rn(v2.z, v2.w);
        __half2 h6 = __floats2half2_rn(v3.x, v3.y);
        __half2 h7 = __floats2half2_rn(v3.z, v3.w);
        uint4 o0, o1;
        o0.x = *reinterpret_cast<uint32_t*>(&h0);
        o0.y = *reinterpret_cast<uint32_t*>(&h1);
        o0.z = *reinterpret_cast<uint32_t*>(&h2);
        o0.w = *reinterpret_cast<uint32_t*>(&h3);
        o1.x = *reinterpret_cast<uint32_t*>(&h4);
        o1.y = *reinterpret_cast<uint32_t*>(&h5);
        o1.z = *reinterpret_cast<uint32_t*>(&h6);
        o1.w = *reinterpret_cast<uint32_t*>(&h7);
        __stcs(reinterpret_cast<uint4*>(g_xh + t * 16), o0);
        __stcs(reinterpret_cast<uint4*>(g_xh + t * 16 + 8), o1);
    } else {
        // W path: 2 consecutive int4 (even index => same quant group).
        uint32_t t  = (blockIdx.x - xblocks) * 512 + threadIdx.x;
        uint32_t i0 = t * 2;               // first int4 index
        uint32_t n   = i0 >> 9;            // 512 int4 per n row
        uint32_t rem = i0 & 511;
        uint32_t g   = rem >> 3;           // group
        uint32_t j4  = rem & 7;            // even: pair stays in-group
        const int4* pk = reinterpret_cast<const int4*>(packed);
        int4 p0 = __ldcs(pk + i0);
        int4 p1 = __ldcs(pk + i0 + 1);
        float rcp = 1.0f / __ldg(scale + n * NUM_GROUPS + g);
        float mv  = __ldg(mn + n * NUM_GROUPS + g);
        int pv[8] = {p0.x, p0.y, p0.z, p0.w, p1.x, p1.y, p1.z, p1.w};
        __half hi[8], lo[8];
#pragma unroll
        for (int b = 0; b < 8; b++) {
            hi[b] = __float2half_rn((float)((pv[b] >> 4) & 0xF) * rcp + mv);
            lo[b] = __float2half_rn((float)(pv[b] & 0xF) * rcp + mv);
        }
        size_t base = (size_t)n * K_DIM + g * 64 + j4 * 4;   // 16B-aligned
        __stcs(reinterpret_cast<uint4*>(g_wh + base),
               *reinterpret_cast<uint4*>(hi));
        __stcs(reinterpret_cast<uint4*>(g_wh + base + 32),
               *reinterpret_cast<uint4*>(lo));
    }
}

// ---------------------------------------------------------------------------
// GEMM: 128 threads (4 warps of 64x64), 3-stage pipeline, occ 2,
// fragment double-buffering across ks.
// ---------------------------------------------------------------------------
__global__ __launch_bounds__(NT, 2)
void gemm_kernel(const float* __restrict__ bias, float* __restrict__ out) {
    extern __shared__ char smem[];
    const uint32_t sb = smem_u32(smem);
    const int tid = threadIdx.x;
    const int lane = tid & 31;
    const int wid = tid >> 5;
    const int warp_m = wid & 1;        // 2 warps along M
    const int warp_n = wid >> 1;       // 2 warps along N
    const int m_base = warp_m * 64;
    const int n_base = warp_n * 64;
    const int m0 = blockIdx.y * BM;
    const int n0 = blockIdx.x * BN;

    // cp.async slots as 32-bit byte offsets from scratch bases
    uint32_t ga_off[8], gb_off[8];
    uint32_t sa[8], sbo[8];
#pragma unroll
    for (int i = 0; i < 8; i++) {
        uint32_t idx = tid + i * NT;
        uint32_t r = idx >> 3, c = idx & 7;
        ga_off[i] = ((uint32_t)(m0 + r) * K_DIM + c * 8) * 2;
        sa[i]     = swz(r, c);
        gb_off[i] = ((uint32_t)(n0 + r) * K_DIM + c * 8) * 2;
        sbo[i]    = A_BYTES + swz(r, c);
    }
    const char* gxb = (const char*)g_xh;
    const char* gwb = (const char*)g_wh;

    float acc[4][8][4];
#pragma unroll
    for (int i = 0; i < 4; i++)
#pragma unroll
        for (int j = 0; j < 8; j++)
#pragma unroll
            for (int q = 0; q < 4; q++) acc[i][j][q] = 0.0f;

    // ldmatrix per-thread row components
    const uint32_t a_row = m_base + (lane & 15);       // + i*16
    const uint32_t a_kh  = (lane >> 4) & 1;
    const uint32_t b_row = n_base + (((lane >> 4) & 1) << 3) + (lane & 7); // + jj*16
    const uint32_t b_kh  = (lane >> 3) & 1;

    // ---- prologue: stages 0..1 ----
#pragma unroll
    for (int s = 0; s < STAGES - 1; s++) {
        uint32_t soff = sb + s * STAGE_BYTES;
        uint32_t koff = (uint32_t)s * BK * 2;   // 128 B per kt
#pragma unroll
        for (int i = 0; i < 8; i++) {
            CP_ASYNC16(soff + sa[i], gxb + ga_off[i] + koff);
            CP_ASYNC16(soff + sbo[i], gwb + gb_off[i] + koff);
        }
        CP_COMMIT();
    }

    uint32_t afr[2][4][4];
    uint32_t bfr[2][8][2];

    // kt loop: unroll 3 == stage period, stage indices compile-time constant
#pragma unroll 3
    for (int kt = 0; kt < KT_COUNT; kt++) {
        const int stage = kt % STAGES;
        CP_WAIT1();
        __syncthreads();

        uint32_t As = sb + stage * STAGE_BYTES;
        uint32_t Bs = As + A_BYTES;

        LOAD_FRAGS(0, 0);

        // ---- ks = 0: MMAs on buf0 overlap LOAD_FRAGS(1) into buf1 ----
        LOAD_FRAGS(1, 1);
#pragma unroll
        for (int i = 0; i < 4; i++)
#pragma unroll
            for (int j = 0; j < 8; j++)
                MMA16816(acc[i][j], afr[0][i], bfr[0][j]);

        // ---- prefetch kt+2 into the stage freed at kt-1 (post ks0 MMA) ----
        {
            int pf = kt + STAGES - 1;
            if (pf < KT_COUNT) {
                const int sp = (stage + 2) % STAGES;
                uint32_t soff = sb + sp * STAGE_BYTES;
                uint32_t koff = (uint32_t)pf * BK * 2;
#pragma unroll
                for (int i = 0; i < 8; i++) {
                    CP_ASYNC16(soff + sa[i], gxb + ga_off[i] + koff);
                    CP_ASYNC16(soff + sbo[i], gwb + gb_off[i] + koff);
                }
            }
            CP_COMMIT();   // empty group when done keeps wait invariant
        }

        // ---- ks = 1: MMAs on buf1 overlap LOAD_FRAGS(2) into buf0 ----
        LOAD_FRAGS(2, 0);
#pragma unroll
        for (int i = 0; i < 4; i++)
#pragma unroll
            for (int j = 0; j < 8; j++)
                MMA16816(acc[i][j], afr[1][i], bfr[1][j]);

        // ---- ks = 2: MMAs on buf0 overlap LOAD_FRAGS(3) into buf1 ----
        LOAD_FRAGS(3, 1);
#pragma unroll
        for (int i = 0; i < 4; i++)
#pragma unroll
            for (int j = 0; j < 8; j++)
                MMA16816(acc[i][j], afr[0][i], bfr[0][j]);

        // ---- ks = 3: MMAs on buf1 ----
#pragma unroll
        for (int i = 0; i < 4; i++)
#pragma unroll
            for (int j = 0; j < 8; j++)
                MMA16816(acc[i][j], afr[1][i], bfr[1][j]);
    }

    // ---- epilogue: bias + streaming stores ----
    const int tq = lane >> 2;          // row within 16
    const int tr = lane & 3;           // col pair
#pragma unroll
    for (int i = 0; i < 4; i++) {
        size_t mrow0 = (size_t)m0 + m_base + i * 16 + tq;
#pragma unroll
        for (int j = 0; j < 8; j++) {
            int ncol = n0 + n_base + j * 8 + tr * 2;
            float2 bv = __ldg(reinterpret_cast<const float2*>(bias + ncol));
            float2 v0 = {acc[i][j][0] + bv.x, acc[i][j][1] + bv.y};
            float2 v1 = {acc[i][j][2] + bv.x, acc[i][j][3] + bv.y};
            __stcs(reinterpret_cast<float2*>(out + mrow0 * N_DIM + ncol), v0);
            __stcs(reinterpret_cast<float2*>(out + (mrow0 + 8) * N_DIM + ncol), v1);
        }
    }
}

// ---------------------------------------------------------------------------
extern "C" void kernel_launch(void* const* d_in, const int* in_sizes, int n_in,
                              void* d_out, int out_size) {
    const float* x      = (const float*)d_in[0];
    const int*   packed = (const int*)d_in[1];
    const float* mn     = (const float*)d_in[2];
    const float* scale  = (const float*)d_in[3];
    const float* bias   = (const float*)d_in[4];
    float* out = (float*)d_out;

    const int M = in_sizes[0] / K_DIM;                 // 8192

    cudaFuncSetAttribute(gemm_kernel,
                         cudaFuncAttributeMaxDynamicSharedMemorySize, SMEM_TOTAL);

    const int xblocks = (int)(((size_t)M * K_DIM / 16) / 512);           // 4096
    const int wblocks = (N_DIM * 512 / 2) / 512;                         // 2048
    prep_kernel<<<xblocks + wblocks, 512>>>(x, packed, mn, scale, xblocks);

    dim3 grid(N_DIM / BN, M / BM);                     // (32, 64)
    gemm_kernel<<<grid, NT, SMEM_TOTAL>>>(bias, out);
}

// round 17
// speedup vs baseline: 1.1132x; 1.0607x over previous
#include <cuda_runtime.h>
#include <cuda_fp16.h>
#include <cstdint>

// ============================================================================
// CLinear: out[M,N] = x[M,K] @ dequant(W)[N,K]^T + bias
// M=8192, N=4096, K=4096. Base-compute_103-safe: mma.sync fp16 + cp.async.
// R17: cross-kt fragment pipelining — ks0 fragments of kt+1 are loaded during
//      ks3 MMAs of kt, removing the post-sync LDSM->MMA bubble at every kt
//      boundary. CP_WAIT1 moved mid-body (waits on a group committed one full
//      iteration earlier => near-zero stall). Everything else = R16 (best:
//      578.0us; 4 warps 64x64, 3 stages, occ 2, frag double-buffer).
// ============================================================================

#define K_DIM 4096
#define N_DIM 4096
#define NUM_GROUPS 64
#define M_MAX 8192

#define BM 128
#define BN 128
#define BK 64
#define KT_COUNT (K_DIM / BK)      // 64
#define STAGES 3
#define A_BYTES (BM * BK * 2)      // 16384
#define B_BYTES (BN * BK * 2)      // 16384
#define STAGE_BYTES (A_BYTES + B_BYTES)          // 32768
#define SMEM_TOTAL (STAGES * STAGE_BYTES)        // 98304 -> 2 CTAs/SM
#define NT 128

// fp16 scratch (device globals: the only legal scratch)
__device__ __half g_xh[(size_t)M_MAX * K_DIM];   // 64 MB
__device__ __half g_wh[(size_t)N_DIM * K_DIM];   // 32 MB

// ---------------------------------------------------------------------------
__device__ __forceinline__ uint32_t smem_u32(const void* p) {
    uint32_t a;
    asm("{ .reg .u64 t; cvta.to.shared.u64 t, %1; cvt.u32.u64 %0, t; }"
        : "=r"(a) : "l"(p));
    return a;
}
// 16B-atom xor swizzle within a 128B row: atom col c (0..7), row r
__device__ __forceinline__ uint32_t swz(uint32_t row, uint32_t c) {
    return row * 128u + ((c ^ (row & 7u)) << 4);
}

#define CP_ASYNC16(dst, src) \
    asm volatile("cp.async.cg.shared.global [%0], [%1], 16;" :: "r"(dst), "l"(src))
#define CP_COMMIT() asm volatile("cp.async.commit_group;")
#define CP_WAIT1()  asm volatile("cp.async.wait_group 1;")

#define LDM_X4(r0, r1, r2, r3, a) \
    asm volatile("ldmatrix.sync.aligned.m8n8.x4.shared.b16 {%0,%1,%2,%3}, [%4];" \
                 : "=r"(r0), "=r"(r1), "=r"(r2), "=r"(r3) : "r"(a))

#define MMA16816(d, a, b)                                                      \
    asm volatile(                                                              \
        "mma.sync.aligned.m16n8k16.row.col.f32.f16.f16.f32 "                   \
        "{%0,%1,%2,%3}, {%4,%5,%6,%7}, {%8,%9}, {%0,%1,%2,%3};"                \
        : "+f"((d)[0]), "+f"((d)[1]), "+f"((d)[2]), "+f"((d)[3])               \
        : "r"((a)[0]), "r"((a)[1]), "r"((a)[2]), "r"((a)[3]),                  \
          "r"((b)[0]), "r"((b)[1]))

// fragment load for ks from smem bases (AsX, BsX) into buffer slot b
#define LOAD_FRAGS_AT(ks, b, AsX, BsX)                                         \
    do {                                                                       \
        _Pragma("unroll")                                                      \
        for (int i = 0; i < 4; i++) {                                          \
            uint32_t addr = (AsX) + swz(a_row + i * 16, (ks) * 2 + a_kh);      \
            LDM_X4(afr[b][i][0], afr[b][i][1], afr[b][i][2], afr[b][i][3], addr); \
        }                                                                      \
        _Pragma("unroll")                                                      \
        for (int jj = 0; jj < 4; jj++) {                                       \
            uint32_t addr = (BsX) + swz(b_row + jj * 16, (ks) * 2 + b_kh);     \
            uint32_t r0, r1, r2, r3;                                           \
            LDM_X4(r0, r1, r2, r3, addr);                                      \
            bfr[b][jj * 2][0] = r0;     bfr[b][jj * 2][1] = r1;                \
            bfr[b][jj * 2 + 1][0] = r2; bfr[b][jj * 2 + 1][1] = r3;            \
        }                                                                      \
    } while (0)

#define MMA_BURST(b)                                                           \
    do {                                                                       \
        _Pragma("unroll")                                                      \
        for (int i = 0; i < 4; i++)                                            \
            _Pragma("unroll")                                                  \
            for (int j = 0; j < 8; j++)                                        \
                MMA16816(acc[i][j], afr[b][i], bfr[b][j]);                     \
    } while (0)

// ---------------------------------------------------------------------------
// fused prep: blocks [0, xblocks) convert x -> fp16 (16 floats/thread);
// the rest dequant W (2 consecutive int4 = 16 weights per thread).
// ---------------------------------------------------------------------------
__global__ __launch_bounds__(512)
void prep_kernel(const float* __restrict__ x,
                 const int* __restrict__ packed,
                 const float* __restrict__ mn,
                 const float* __restrict__ scale,
                 int xblocks) {
    if ((int)blockIdx.x < xblocks) {
        // x path: 4 float4 in -> 2 uint4 (16 fp16) out
        size_t t = (size_t)blockIdx.x * 512 + threadIdx.x;
        const float4* xv = reinterpret_cast<const float4*>(x);
        float4 v0 = __ldcs(xv + t * 4);
        float4 v1 = __ldcs(xv + t * 4 + 1);
        float4 v2 = __ldcs(xv + t * 4 + 2);
        float4 v3 = __ldcs(xv + t * 4 + 3);
        __half2 h0 = __floats2half2_rn(v0.x, v0.y);
        __half2 h1 = __floats2half2_rn(v0.z, v0.w);
        __half2 h2 = __floats2half2_rn(v1.x, v1.y);
        __half2 h3 = __floats2half2_rn(v1.z, v1.w);
        __half2 h4 = __floats2half2_rn(v2.x, v2.y);
        __half2 h5 = __floats2half2_rn(v2.z, v2.w);
        __half2 h6 = __floats2half2_rn(v3.x, v3.y);
        __half2 h7 = __floats2half2_rn(v3.z, v3.w);
        uint4 o0, o1;
        o0.x = *reinterpret_cast<uint32_t*>(&h0);
        o0.y = *reinterpret_cast<uint32_t*>(&h1);
        o0.z = *reinterpret_cast<uint32_t*>(&h2);
        o0.w = *reinterpret_cast<uint32_t*>(&h3);
        o1.x = *reinterpret_cast<uint32_t*>(&h4);
        o1.y = *reinterpret_cast<uint32_t*>(&h5);
        o1.z = *reinterpret_cast<uint32_t*>(&h6);
        o1.w = *reinterpret_cast<uint32_t*>(&h7);
        __stcs(reinterpret_cast<uint4*>(g_xh + t * 16), o0);
        __stcs(reinterpret_cast<uint4*>(g_xh + t * 16 + 8), o1);
    } else {
        // W path: 2 consecutive int4 (even index => same quant group).
        uint32_t t  = (blockIdx.x - xblocks) * 512 + threadIdx.x;
        uint32_t i0 = t * 2;               // first int4 index
        uint32_t n   = i0 >> 9;            // 512 int4 per n row
        uint32_t rem = i0 & 511;
        uint32_t g   = rem >> 3;           // group
        uint32_t j4  = rem & 7;            // even: pair stays in-group
        const int4* pk = reinterpret_cast<const int4*>(packed);
        int4 p0 = __ldcs(pk + i0);
        int4 p1 = __ldcs(pk + i0 + 1);
        float rcp = 1.0f / __ldg(scale + n * NUM_GROUPS + g);
        float mv  = __ldg(mn + n * NUM_GROUPS + g);
        int pv[8] = {p0.x, p0.y, p0.z, p0.w, p1.x, p1.y, p1.z, p1.w};
        __half hi[8], lo[8];
#pragma unroll
        for (int b = 0; b < 8; b++) {
            hi[b] = __float2half_rn((float)((pv[b] >> 4) & 0xF) * rcp + mv);
            lo[b] = __float2half_rn((float)(pv[b] & 0xF) * rcp + mv);
        }
        size_t base = (size_t)n * K_DIM + g * 64 + j4 * 4;   // 16B-aligned
        __stcs(reinterpret_cast<uint4*>(g_wh + base),
               *reinterpret_cast<uint4*>(hi));
        __stcs(reinterpret_cast<uint4*>(g_wh + base + 32),
               *reinterpret_cast<uint4*>(lo));
    }
}

// ---------------------------------------------------------------------------
// GEMM: 128 threads (4 warps of 64x64), 3-stage pipeline, occ 2,
// cross-kt fragment pipelining.
// ---------------------------------------------------------------------------
__global__ __launch_bounds__(NT, 2)
void gemm_kernel(const float* __restrict__ bias, float* __restrict__ out) {
    extern __shared__ char smem[];
    const uint32_t sb = smem_u32(smem);
    const int tid = threadIdx.x;
    const int lane = tid & 31;
    const int wid = tid >> 5;
    const int warp_m = wid & 1;        // 2 warps along M
    const int warp_n = wid >> 1;       // 2 warps along N
    const int m_base = warp_m * 64;
    const int n_base = warp_n * 64;
    const int m0 = blockIdx.y * BM;
    const int n0 = blockIdx.x * BN;

    // cp.async slots as 32-bit byte offsets from scratch bases
    uint32_t ga_off[8], gb_off[8];
    uint32_t sa[8], sbo[8];
#pragma unroll
    for (int i = 0; i < 8; i++) {
        uint32_t idx = tid + i * NT;
        uint32_t r = idx >> 3, c = idx & 7;
        ga_off[i] = ((uint32_t)(m0 + r) * K_DIM + c * 8) * 2;
        sa[i]     = swz(r, c);
        gb_off[i] = ((uint32_t)(n0 + r) * K_DIM + c * 8) * 2;
        sbo[i]    = A_BYTES + swz(r, c);
    }
    const char* gxb = (const char*)g_xh;
    const char* gwb = (const char*)g_wh;

    float acc[4][8][4];
#pragma unroll
    for (int i = 0; i < 4; i++)
#pragma unroll
        for (int j = 0; j < 8; j++)
#pragma unroll
            for (int q = 0; q < 4; q++) acc[i][j][q] = 0.0f;

    // ldmatrix per-thread row components
    const uint32_t a_row = m_base + (lane & 15);       // + i*16
    const uint32_t a_kh  = (lane >> 4) & 1;
    const uint32_t b_row = n_base + (((lane >> 4) & 1) << 3) + (lane & 7); // + jj*16
    const uint32_t b_kh  = (lane >> 3) & 1;

    // ---- prologue: fill stages 0..1 ----
#pragma unroll
    for (int s = 0; s < STAGES - 1; s++) {
        uint32_t soff = sb + s * STAGE_BYTES;
        uint32_t koff = (uint32_t)s * BK * 2;   // 128 B per kt
#pragma unroll
        for (int i = 0; i < 8; i++) {
            CP_ASYNC16(soff + sa[i], gxb + ga_off[i] + koff);
            CP_ASYNC16(soff + sbo[i], gwb + gb_off[i] + koff);
        }
        CP_COMMIT();
    }

    uint32_t afr[2][4][4];
    uint32_t bfr[2][8][2];

    // prologue: wait for kt0 data, preload its ks0 fragments into buf0
    CP_WAIT1();
    __syncthreads();
    LOAD_FRAGS_AT(0, 0, sb, sb + A_BYTES);

    // kt loop. Steady-state invariant: buf0 holds ks0 fragments of kt.
    // Per iter: ldF1->MMA0, sync+prefetch, ldF2->MMA1, WAIT1 (kt+1 data,
    // committed one iter ago), ldF3->MMA2, ldF0(kt+1)->MMA3.
#pragma unroll 3
    for (int kt = 0; kt < KT_COUNT; kt++) {
        const int stage = kt % STAGES;
        const uint32_t As = sb + stage * STAGE_BYTES;
        const uint32_t Bs = As + A_BYTES;

        // ks1 fragments overlap ks0 MMAs
        LOAD_FRAGS_AT(1, 1, As, Bs);
        MMA_BURST(0);                      // ks0

        // barrier separates all warps' reads of stage sp (done in iter kt-1)
        // from this iteration's prefetch writes into it
        __syncthreads();
        {
            int pf = kt + STAGES - 1;
            if (pf < KT_COUNT) {
                const int sp = (stage + 2) % STAGES;
                uint32_t soff = sb + sp * STAGE_BYTES;
                uint32_t koff = (uint32_t)pf * BK * 2;
#pragma unroll
                for (int i = 0; i < 8; i++) {
                    CP_ASYNC16(soff + sa[i], gxb + ga_off[i] + koff);
                    CP_ASYNC16(soff + sbo[i], gwb + gb_off[i] + koff);
                }
            }
            CP_COMMIT();   // empty group when done keeps wait invariant
        }

        LOAD_FRAGS_AT(2, 0, As, Bs);
        MMA_BURST(1);                      // ks1

        // ensure kt+1 stage data arrived (group committed at iter kt-1;
        // one full kt of MMA time has elapsed -> near-zero stall)
        CP_WAIT1();

        LOAD_FRAGS_AT(3, 1, As, Bs);
        MMA_BURST(0);                      // ks2

        // preload ks0 of kt+1 into buf0 during ks3 MMAs
        if (kt + 1 < KT_COUNT) {
            const int stn = (kt + 1) % STAGES;
            const uint32_t Asn = sb + stn * STAGE_BYTES;
            LOAD_FRAGS_AT(0, 0, Asn, Asn + A_BYTES);
        }
        MMA_BURST(1);                      // ks3
    }

    // ---- epilogue: bias + streaming stores ----
    const int tq = lane >> 2;          // row within 16
    const int tr = lane & 3;           // col pair
#pragma unroll
    for (int i = 0; i < 4; i++) {
        size_t mrow0 = (size_t)m0 + m_base + i * 16 + tq;
#pragma unroll
        for (int j = 0; j < 8; j++) {
            int ncol = n0 + n_base + j * 8 + tr * 2;
            float2 bv = __ldg(reinterpret_cast<const float2*>(bias + ncol));
            float2 v0 = {acc[i][j][0] + bv.x, acc[i][j][1] + bv.y};
            float2 v1 = {acc[i][j][2] + bv.x, acc[i][j][3] + bv.y};
            __stcs(reinterpret_cast<float2*>(out + mrow0 * N_DIM + ncol), v0);
            __stcs(reinterpret_cast<float2*>(out + (mrow0 + 8) * N_DIM + ncol), v1);
        }
    }
}

// ---------------------------------------------------------------------------
extern "C" void kernel_launch(void* const* d_in, const int* in_sizes, int n_in,
                              void* d_out, int out_size) {
    const float* x      = (const float*)d_in[0];
    const int*   packed = (const int*)d_in[1];
    const float* mn     = (const float*)d_in[2];
    const float* scale  = (const float*)d_in[3];
    const float* bias   = (const float*)d_in[4];
    float* out = (float*)d_out;

    const int M = in_sizes[0] / K_DIM;                 // 8192

    cudaFuncSetAttribute(gemm_kernel,
                         cudaFuncAttributeMaxDynamicSharedMemorySize, SMEM_TOTAL);

    const int xblocks = (int)(((size_t)M * K_DIM / 16) / 512);           // 4096
    const int wblocks = (N_DIM * 512 / 2) / 512;                         // 2048
    prep_kernel<<<xblocks + wblocks, 512>>>(x, packed, mn, scale, xblocks);

    dim3 grid(N_DIM / BN, M / BM);                     // (32, 64)
    gemm_kernel<<<grid, NT, SMEM_TOTAL>>>(bias, out);
}